// round 13
// baseline (speedup 1.0000x reference)
#include <cuda_runtime.h>
#include <cstdint>
#include <cstddef>

using ull = unsigned long long;

#define THREADS  576
#define HTHREADS 288               // threads per independent half
#define NCH      256
#define CK       8
#define NSTAGE   (NCH / CK)        // 32
#define H        64
#define W        64
#define YROWS    24                // 16 + 2*4 halo
#define YSTR     28                // floats; conflict-free, rows 16B-aligned
#define XSTR     20                // floats; conflict-free, rows 16B-aligned
#define YS_BUF   (CK * YROWS * YSTR)   // 5376 floats
#define XS_BUF   (CK * 16 * XSTR)      // 2560 floats
#define BUF_FLOATS (YS_BUF + XS_BUF)   // 7936
#define BUF_BYTES  (BUF_FLOATS * 4)    // 31744
#define HALF_BYTES (3 * BUF_BYTES)     // 95232 (3-stage pipeline)
#define SMEM_BYTES (2 * HALF_BYTES)    // 190464

#define YCH_B (YROWS * YSTR * 4)   // 2688 B per channel of y
#define XCH_B (16 * XSTR * 4)      // 1280 B per channel of x
#define NYV   (CK * YROWS * 6)     // 1152 vec4 y-loads per stage (= 4*288 exactly)
#define NXV   (CK * 16 * 4)        // 512 vec4 x-loads per stage

// ---- async copy helpers (zfill gives the zero-padded halo for free) ----
__device__ __forceinline__ void cp16(uint32_t dst, const float* src, int ok) {
    asm volatile("cp.async.cg.shared.global [%0], [%1], 16, %2;\n"
                 :: "r"(dst), "l"(src), "r"(ok ? 16 : 0));
}
__device__ __forceinline__ void cp_commit() { asm volatile("cp.async.commit_group;\n"); }
__device__ __forceinline__ void cp_wait1()  { asm volatile("cp.async.wait_group 1;\n"); }

// half-scoped barrier: two independent 288-thread domains in one CTA
__device__ __forceinline__ void hbar(int id) {
    asm volatile("bar.sync %0, %1;" :: "r"(id), "r"(HTHREADS) : "memory");
}

// ---- packed f32x2 math (FFMA2 is PTX-only on sm_103a) ----
__device__ __forceinline__ void fma2(ull& acc, ull a, ull b) {
    asm("fma.rn.f32x2 %0, %1, %2, %0;" : "+l"(acc) : "l"(a), "l"(b));
}
__device__ __forceinline__ ull mul2(ull a, ull b) {
    ull d;
    asm("mul.rn.f32x2 %0, %1, %2;" : "=l"(d) : "l"(a), "l"(b));
    return d;
}
__device__ __forceinline__ ull shft(ull lo, ull hi) {
    return (lo >> 32) | (hi << 32);   // odd-offset f32 pair {lo.hi, hi.lo}
}
// 16B shared load as two u64 (adjacent f32 pairs)
#define LDSV2(a, b, addr) \
    asm volatile("ld.shared.v2.u64 {%0, %1}, [%2];" : "=l"(a), "=l"(b) : "r"(addr))

__global__ __launch_bounds__(THREADS, 1)
void corr_kernel(const float* __restrict__ xg, const float* __restrict__ yg,
                 float* __restrict__ out) {
    extern __shared__ float sm[];

    const int tid = threadIdx.x;
    const int h   = (tid >= HTHREADS);      // which independent half
    const int ht  = tid - h * HTHREADS;     // 0..287 within half

    const int bb   = blockIdx.x >> 3;       // batch
    const int t    = blockIdx.x & 7;        // tile-pair index
    const int tix  = t * 2 + h;             // 0..15 in a 4x4 grid of 16x16 tiles
    const int i0   = (tix >> 2) * 16;
    const int j0   = (tix & 3) * 16;

    const int di   = ht >> 5;               // warp within half = displacement row
    const int lane = ht & 31;
    const int gi   = lane & 15;             // pixel row within tile
    const int jl   = (lane >> 4) * 8;       // 8-wide pixel strip: 0 or 8

    const uint32_t hb = (uint32_t)__cvta_generic_to_shared(sm)
                      + (uint32_t)h * HALF_BYTES;

    // acc[dj*4 + m] = packed pixels (jl+2m, jl+2m+1) at displacement (di, dj)
    ull acc[36];
#pragma unroll
    for (int k = 0; k < 36; k++) acc[k] = 0ULL;

    // ---------------- stage loader (per half) ----------------
    auto load_stage = [&](int s, int buf) {
        const uint32_t yb = hb + (uint32_t)buf * BUF_BYTES;
        const uint32_t xb = yb + (uint32_t)YS_BUF * 4u;
        const float* ygs = yg + ((size_t)(bb * NCH + s * CK)) * (H * W);
        const float* xgs = xg + ((size_t)(bb * NCH + s * CK)) * (H * W);
#pragma unroll
        for (int k = 0; k < 4; k++) {        // 1152 = 4*288 exactly, no tail
            int idx = ht + k * HTHREADS;
            int cc  = idx / (YROWS * 6);
            int rem = idx - cc * (YROWS * 6);
            int r   = rem / 6;
            int q   = rem - r * 6;
            int gr  = i0 + r - 4;
            int gc  = j0 - 4 + 4 * q;
            int ok  = (gr >= 0) & (gr < H) & (gc >= 0) & (gc < W);
            const float* src = ygs + ((cc * H + (ok ? gr : 0)) * W + (ok ? gc : 0));
            cp16(yb + (uint32_t)((cc * YROWS + r) * YSTR + 4 * q) * 4u, src, ok);
        }
#pragma unroll
        for (int k = 0; k < 2; k++) {        // 512 loads: tail on k=1
            if (k == 0 || ht < NXV - HTHREADS) {
                int idx = ht + k * HTHREADS;
                int cc  = idx >> 6;           // / 64
                int r   = (idx >> 2) & 15;
                int q   = idx & 3;
                const float* src = xgs + ((cc * H + i0 + r) * W + j0 + 4 * q);
                cp16(xb + (uint32_t)((cc * 16 + r) * XSTR + 4 * q) * 4u, src, 1);
            }
        }
        cp_commit();
    };

    // ---------------- 3-stage pipeline (independent per half) ----------------
    load_stage(0, 0);
    load_stage(1, 1);

    const uint32_t yoff = (uint32_t)((gi + di) * YSTR + jl) * 4u;
    const uint32_t xoff = (uint32_t)(YS_BUF + gi * XSTR + jl) * 4u;
    const int barid = 1 + h;

    int buf = 0, lbuf = 2;
#pragma unroll 1
    for (int s = 0; s < NSTAGE; s++) {
        cp_wait1();            // own groups <= s complete (s issued 2 stages ago)
        hbar(barid);           // half-scoped: stage s visible, reads of s-1 done
        if (s + 2 < NSTAGE) load_stage(s + 2, lbuf);
        else cp_commit();      // keep per-thread group accounting for wait1

        const uint32_t ya = hb + (uint32_t)buf * BUF_BYTES + yoff;
        const uint32_t xa = hb + (uint32_t)buf * BUF_BYTES + xoff;

#pragma unroll
        for (int cc = 0; cc < CK; cc++) {
            ull w[8], xp[4], sp[7];
            LDSV2(w[0], w[1], ya + cc * YCH_B);
            LDSV2(w[2], w[3], ya + cc * YCH_B + 16);
            LDSV2(w[4], w[5], ya + cc * YCH_B + 32);
            LDSV2(w[6], w[7], ya + cc * YCH_B + 48);
            LDSV2(xp[0], xp[1], xa + cc * XCH_B);
            LDSV2(xp[2], xp[3], xa + cc * XCH_B + 16);

            // m-major with JIT odd-pair creation (R8-proven schedule)
#pragma unroll
            for (int m = 0; m < 4; m++) {
                if (m == 0) {
#pragma unroll
                    for (int q = 0; q < 4; q++) sp[q] = shft(w[q], w[q + 1]);
                } else {
                    sp[m + 3] = shft(w[m + 3], w[m + 4]);
                }
#pragma unroll
                for (int dj = 0; dj < 9; dj++) {
                    const int o = 2 * m + dj;   // compile-time, max 14
                    fma2(acc[dj * 4 + m], xp[m], (o & 1) ? sp[o >> 1] : w[o >> 1]);
                }
            }
        }

        buf  = (buf == 2) ? 0 : buf + 1;
        lbuf = (lbuf == 2) ? 0 : lbuf + 1;
    }

    // ---------------- epilogue: scale by 1/C, store ----------------
    const uint32_t su = __float_as_uint(1.0f / 256.0f);
    const ull scl = ((ull)su << 32) | su;
#pragma unroll
    for (int dj = 0; dj < 9; dj++) {
        float* op = out + (((size_t)bb * 81 + di * 9 + dj) * H + (i0 + gi)) * W
                        + j0 + jl;
        ulonglong2 v;
        v.x = mul2(acc[dj * 4 + 0], scl);
        v.y = mul2(acc[dj * 4 + 1], scl);
        ((ulonglong2*)op)[0] = v;
        v.x = mul2(acc[dj * 4 + 2], scl);
        v.y = mul2(acc[dj * 4 + 3], scl);
        ((ulonglong2*)op)[1] = v;
    }
}

extern "C" void kernel_launch(void* const* d_in, const int* in_sizes, int n_in,
                              void* d_out, int out_size) {
    (void)in_sizes; (void)n_in; (void)out_size;
    const float* x = (const float*)d_in[0];
    const float* y = (const float*)d_in[1];
    cudaFuncSetAttribute(corr_kernel, cudaFuncAttributeMaxDynamicSharedMemorySize,
                         SMEM_BYTES);
    corr_kernel<<<16 * 8, THREADS, SMEM_BYTES>>>(x, y, (float*)d_out);
}